// round 1
// baseline (speedup 1.0000x reference)
#include <cuda_runtime.h>
#include <cstdint>

#define NVOX 40000
#define CCH  128
#define BM   64
#define BK   32
#define BN   128
#define ASTR 68   // padded A stride (floats): conflict-free + 16B aligned rows

// Persistent device scratch (zero-initialized at module load; pad row of g_h1
// and g_zero are never written, so they stay zero across graph replays).
__device__ float g_h1[(NVOX + 1) * CCH];
__device__ float g_Wc[8 * 8 * CCH * CCH];
__device__ float g_zero[CCH];

// ---------------------------------------------------------------------------
// Build combined child weights:
//   Wc[c][t][i][j] = sum over conv offsets `off` with floor((c+off)/2) == d(t)
// Per axis: c=0: t=0 -> off{-1}, t=1 -> off{0,1}
//           c=1: t=0 -> off{-1,0}, t=1 -> off{1}
// ---------------------------------------------------------------------------
__global__ void build_wc(const float* __restrict__ W2) {
    int e = blockIdx.x * 256 + threadIdx.x;
    if (e >= 8 * 8 * CCH * CCH) return;
    int j = e & 127;
    int i = (e >> 7) & 127;
    int t = (e >> 14) & 7;
    int c = (e >> 17) & 7;

    int lo[3], hi[3];
    #pragma unroll
    for (int a = 0; a < 3; a++) {
        int cb = (c >> (2 - a)) & 1;
        int tb = (t >> (2 - a)) & 1;
        if (cb == 0) { if (tb == 0) { lo[a] = -1; hi[a] = -1; } else { lo[a] = 0; hi[a] = 1; } }
        else         { if (tb == 0) { lo[a] = -1; hi[a] = 0;  } else { lo[a] = 1; hi[a] = 1; } }
    }
    float acc = 0.f;
    for (int o0 = lo[0]; o0 <= hi[0]; o0++)
        for (int o1 = lo[1]; o1 <= hi[1]; o1++)
            for (int o2 = lo[2]; o2 <= hi[2]; o2++) {
                int k = (o0 + 1) * 9 + (o1 + 1) * 3 + (o2 + 1);
                acc += W2[(size_t)k * CCH * CCH + i * CCH + j];
            }
    g_Wc[e] = acc;
}

// ---------------------------------------------------------------------------
// Generic gathered sparse-conv GEMM + bias + SiLU.
// Tile: BM=64 rows x BN=128 cols per CTA, BK=32 K-chunk, 256 threads,
// 4x8 register microtile per thread.
// is_l2==0: taps t=0..26, W = Wext[t], gather rows feats[nbr[m][t]] (pad->0)
// is_l2==1: blockIdx.y = child c, taps t=0..7 mapped to parent offset kd(c,t),
//           W = g_Wc[c][t], gather h1[nbr[m][kd]] (pad row is physical zeros)
// ---------------------------------------------------------------------------
__global__ __launch_bounds__(256) void sconv(
    const float* __restrict__ src, int srcRows,
    const int*  __restrict__ nbr,
    const float* __restrict__ Wext,
    const float* __restrict__ bias,
    float* __restrict__ outb, long long ostride,
    int ntaps, int is_l2)
{
    __shared__ __align__(16) float As[BK][ASTR];
    __shared__ __align__(16) float Bs[BK][BN];

    const int tid = threadIdx.x;
    const int m0  = blockIdx.x * BM;
    const int child = is_l2 ? (int)blockIdx.y : -1;

    // loader roles
    const int arow = tid & 63;   // A: gathered row
    const int aq   = tid >> 6;   // A: col octet (aq*8 .. aq*8+7 of chunk)
    const int brow = tid >> 3;   // B: weight row within chunk
    const int bq   = tid & 7;    // B: float4 column phase
    // compute roles
    const int rt = tid >> 4;     // rows rt*4 .. rt*4+3
    const int ct = tid & 15;     // cols ct*8 .. ct*8+7

    float acc[4][8];
    #pragma unroll
    for (int i = 0; i < 4; i++)
        #pragma unroll
        for (int j = 0; j < 8; j++) acc[i][j] = 0.f;

    const int nbr_row = (m0 + arow) * 27;

    #pragma unroll 1
    for (int t = 0; t < ntaps; t++) {
        int tk;
        const float* Wt;
        if (child >= 0) {
            int d0 = ((child >> 2) & 1) ? ((t >> 2) & 1) : (((t >> 2) & 1) - 1);
            int d1 = ((child >> 1) & 1) ? ((t >> 1) & 1) : (((t >> 1) & 1) - 1);
            int d2 = (child & 1)        ? (t & 1)        : ((t & 1) - 1);
            tk = (d0 + 1) * 9 + (d1 + 1) * 3 + (d2 + 1);
            Wt = g_Wc + (size_t)(child * 8 + t) * (CCH * CCH);
        } else {
            tk = t;
            Wt = Wext + (size_t)t * (CCH * CCH);
        }
        const int idx = nbr[nbr_row + tk];
        const float* arowp = (idx < srcRows) ? (src + (size_t)idx * CCH) : g_zero;

        #pragma unroll 1
        for (int cc = 0; cc < CCH; cc += BK) {
            // issue global loads before the barrier (overlap w/ prior compute)
            float4 a0 = *(const float4*)(arowp + cc + aq * 8);
            float4 a1 = *(const float4*)(arowp + cc + aq * 8 + 4);
            const float* wr = Wt + (size_t)(cc + brow) * CCH;
            float4 w0 = *(const float4*)(wr + bq * 4);
            float4 w1 = *(const float4*)(wr + (bq + 8) * 4);
            float4 w2 = *(const float4*)(wr + (bq + 16) * 4);
            float4 w3 = *(const float4*)(wr + (bq + 24) * 4);

            __syncthreads();  // previous epoch's smem reads complete
            As[aq * 8 + 0][arow] = a0.x; As[aq * 8 + 1][arow] = a0.y;
            As[aq * 8 + 2][arow] = a0.z; As[aq * 8 + 3][arow] = a0.w;
            As[aq * 8 + 4][arow] = a1.x; As[aq * 8 + 5][arow] = a1.y;
            As[aq * 8 + 6][arow] = a1.z; As[aq * 8 + 7][arow] = a1.w;
            *(float4*)&Bs[brow][bq * 4]        = w0;
            *(float4*)&Bs[brow][(bq + 8) * 4]  = w1;
            *(float4*)&Bs[brow][(bq + 16) * 4] = w2;
            *(float4*)&Bs[brow][(bq + 24) * 4] = w3;
            __syncthreads();

            #pragma unroll
            for (int kk = 0; kk < BK; kk++) {
                float4 av  = *(const float4*)&As[kk][rt * 4];
                float4 bva = *(const float4*)&Bs[kk][ct * 8];
                float4 bvb = *(const float4*)&Bs[kk][ct * 8 + 4];
                float a[4] = {av.x, av.y, av.z, av.w};
                float b[8] = {bva.x, bva.y, bva.z, bva.w, bvb.x, bvb.y, bvb.z, bvb.w};
                #pragma unroll
                for (int i = 0; i < 4; i++)
                    #pragma unroll
                    for (int j = 0; j < 8; j++)
                        acc[i][j] = fmaf(a[i], b[j], acc[i][j]);
            }
        }
    }

    // epilogue: bias + SiLU + store
    float bv[8];
    #pragma unroll
    for (int j = 0; j < 8; j++) bv[j] = bias[ct * 8 + j];
    const long long coff = (child >= 0) ? (long long)child * CCH : 0;

    #pragma unroll
    for (int i = 0; i < 4; i++) {
        int m = m0 + rt * 4 + i;
        float* op = outb + (long long)m * ostride + coff + ct * 8;
        float tmp[8];
        #pragma unroll
        for (int j = 0; j < 8; j++) {
            float x = acc[i][j] + bv[j];
            tmp[j] = x / (1.f + __expf(-x));
        }
        *(float4*)op       = make_float4(tmp[0], tmp[1], tmp[2], tmp[3]);
        *(float4*)(op + 4) = make_float4(tmp[4], tmp[5], tmp[6], tmp[7]);
    }
}

// ---------------------------------------------------------------------------
extern "C" void kernel_launch(void* const* d_in, const int* in_sizes, int n_in,
                              void* d_out, int out_size) {
    const float* feats = (const float*)d_in[0];
    const float* W1    = (const float*)d_in[1];
    const float* b1    = (const float*)d_in[2];
    const float* W2    = (const float*)d_in[3];
    const float* b2    = (const float*)d_in[4];
    const int*   nbr1  = (const int*)d_in[5];
    // d_in[6] (nbr2) intentionally unused: layer-2 is re-indexed onto the
    // parent graph via the subdivide structure.
    float* out = (float*)d_out;
    (void)in_sizes; (void)n_in; (void)out_size;

    void* h1p = nullptr;
    cudaGetSymbolAddress(&h1p, g_h1);  // query only, no allocation, capture-safe

    // 1) combined child weights Wc[8][8][128][128]
    build_wc<<<(8 * 8 * CCH * CCH + 255) / 256, 256>>>(W2);

    // 2) layer 1: 27 taps, feats -> h1 (pad row of g_h1 stays zero)
    sconv<<<dim3(NVOX / BM, 1), 256>>>(feats, NVOX, nbr1, W1, b1,
                                       (float*)h1p, CCH, 27, 0);

    // 3) layer 2: 8 children x 8 parent taps, h1 -> out[8m+c]
    sconv<<<dim3(NVOX / BM, 8), 256>>>((const float*)h1p, NVOX + 1, nbr1,
                                       nullptr, b2, out, 8 * CCH, 8, 1);
}

// round 3
// speedup vs baseline: 2.8351x; 2.8351x over previous
#include <cuda_runtime.h>
#include <cuda_bf16.h>
#include <cstdint>

#define NVOX 40000
#define CCH  128
#define K27  27
#define BMT  128
#define GRIDM ((NVOX + BMT - 1) / BMT)   // 313

#define KCH   64                 // K per stage chunk
#define ASTRB 144                // padded row stride bytes (72 bf16)
#define TILE_B (128 * ASTRB)     // 18432 B per tile (A rows or B cols)
#define STAGE  (4 * TILE_B)      // Ah, Al, Bh, Bl
#define SMEM_BYTES (2 * STAGE)   // 147456

// ---------------- persistent device scratch (zero-init) ---------------------
__device__ __nv_bfloat16 g_h1h[(NVOX + 1) * CCH];   // layer-1 out hi (pad row 0)
__device__ __nv_bfloat16 g_h1l[(NVOX + 1) * CCH];   // layer-1 out lo
__device__ float g_zero[CCH];                        // fp32 zero row (l1 pad)
__device__ __nv_bfloat16 g_w1h[K27 * CCH * CCH];     // W1^T [k][cout][cin] hi
__device__ __nv_bfloat16 g_w1l[K27 * CCH * CCH];
__device__ __nv_bfloat16 g_wch[64 * CCH * CCH];      // Wc [c][t][cout][cin] hi
__device__ __nv_bfloat16 g_wcl[64 * CCH * CCH];

// ---------------- helpers ----------------------------------------------------
__device__ __forceinline__ uint32_t smem_u32(const void* p) {
    uint32_t a;
    asm("{ .reg .u64 t; cvta.to.shared.u64 t, %1; cvt.u32.u64 %0, t; }" : "=r"(a) : "l"(p));
    return a;
}
__device__ __forceinline__ void bf16_split(float x, __nv_bfloat16& h, __nv_bfloat16& l) {
    h = __float2bfloat16_rn(x);
    l = __float2bfloat16_rn(x - __bfloat162float(h));
}
__device__ __forceinline__ uint32_t pack2(__nv_bfloat16 a, __nv_bfloat16 b) {
    uint32_t r;
    uint16_t ua = *(uint16_t*)&a, ub = *(uint16_t*)&b;
    r = (uint32_t)ua | ((uint32_t)ub << 16);
    return r;
}
__device__ __forceinline__ void sts128(uint32_t a, uint32_t x, uint32_t y, uint32_t z, uint32_t w) {
    asm volatile("st.shared.v4.b32 [%0], {%1,%2,%3,%4};" :: "r"(a), "r"(x), "r"(y), "r"(z), "r"(w) : "memory");
}
__device__ __forceinline__ uint32_t lds32(uint32_t a) {
    uint32_t v;
    asm volatile("ld.shared.b32 %0, [%1];" : "=r"(v) : "r"(a));
    return v;
}
#define CP16(dst, src) asm volatile("cp.async.cg.shared.global [%0], [%1], 16;" :: "r"(dst), "l"(src) : "memory")
#define CP_COMMIT()    asm volatile("cp.async.commit_group;" ::: "memory")
#define CP_WAIT0()     asm volatile("cp.async.wait_group 0;" ::: "memory")

__device__ __forceinline__ void mma_bf16(float* c, const uint32_t* a, const uint32_t* b) {
    asm volatile("mma.sync.aligned.m16n8k16.row.col.f32.bf16.bf16.f32 "
        "{%0,%1,%2,%3}, {%4,%5,%6,%7}, {%8,%9}, {%0,%1,%2,%3};"
        : "+f"(c[0]), "+f"(c[1]), "+f"(c[2]), "+f"(c[3])
        : "r"(a[0]), "r"(a[1]), "r"(a[2]), "r"(a[3]), "r"(b[0]), "r"(b[1]));
}

// ---------------- weight prep -------------------------------------------------
__global__ void prep_w1(const float* __restrict__ W1) {
    int e = blockIdx.x * 256 + threadIdx.x;
    if (e >= K27 * CCH * CCH) return;
    int j = e & 127, i = (e >> 7) & 127, k = e >> 14;   // W1[k][i=cin][j=cout]
    __nv_bfloat16 h, l; bf16_split(W1[e], h, l);
    int o = (k * CCH + j) * CCH + i;                    // [k][cout][cin]
    g_w1h[o] = h; g_w1l[o] = l;
}

__global__ void prep_wc(const float* __restrict__ W2) {
    int e = blockIdx.x * 256 + threadIdx.x;
    if (e >= 64 * CCH * CCH) return;
    int j = e & 127, i = (e >> 7) & 127, t = (e >> 14) & 7, c = e >> 17;
    int lo_[3], hi_[3];
    #pragma unroll
    for (int a = 0; a < 3; a++) {
        int cb = (c >> (2 - a)) & 1, tb = (t >> (2 - a)) & 1;
        if (cb == 0) { if (tb == 0) { lo_[a] = -1; hi_[a] = -1; } else { lo_[a] = 0; hi_[a] = 1; } }
        else         { if (tb == 0) { lo_[a] = -1; hi_[a] = 0;  } else { lo_[a] = 1; hi_[a] = 1; } }
    }
    float acc = 0.f;
    for (int o0 = lo_[0]; o0 <= hi_[0]; o0++)
        for (int o1 = lo_[1]; o1 <= hi_[1]; o1++)
            for (int o2 = lo_[2]; o2 <= hi_[2]; o2++) {
                int k = (o0 + 1) * 9 + (o1 + 1) * 3 + (o2 + 1);
                acc += W2[((size_t)k * CCH + i) * CCH + j];
            }
    __nv_bfloat16 h, l; bf16_split(acc, h, l);
    int o = (((c << 3) + t) * CCH + j) * CCH + i;       // [c][t][cout][cin]
    g_wch[o] = h; g_wcl[o] = l;
}

// ---------------- fused gather-GEMM (bf16 split-3 on mma.sync) ----------------
// IS_L2=0: 27 taps, A = feats fp32 (split inline), out -> g_h1h/g_h1l (+SiLU)
// IS_L2=1: 8 taps/child (blockIdx.y), A = pre-split h1 bf16, out -> fp32 d_out
template <int IS_L2>
__global__ __launch_bounds__(256, 1) void conv_mma(
    const float* __restrict__ srcF,
    const __nv_bfloat16* __restrict__ srcH, const __nv_bfloat16* __restrict__ srcL,
    const int* __restrict__ nbr,
    const __nv_bfloat16* __restrict__ wh, const __nv_bfloat16* __restrict__ wl,
    const float* __restrict__ bias,
    float* __restrict__ outF,
    __nv_bfloat16* __restrict__ outH, __nv_bfloat16* __restrict__ outL)
{
    extern __shared__ __align__(16) unsigned char smem_raw[];
    const uint32_t sb = smem_u32(smem_raw);

    const int tid  = threadIdx.x;
    const int wid  = tid >> 5, lane = tid & 31;
    const int g    = lane >> 2, t4 = lane & 3;
    const int m0   = blockIdx.x * BMT;
    const int child = IS_L2 ? (int)blockIdx.y : 0;
    const int ntaps = IS_L2 ? 8 : 27;
    const int niter = ntaps * 2;          // 2 chunks of K=64 per tap

    // loader roles: A: 2 threads per row; B: 2 threads per cout row
    const int ar = tid >> 1, aseg = tid & 1;
    const int am = m0 + ar;

    // compute roles: warp tile 64(M) x 32(N); warps 2x4
    const int m0w = (wid >> 2) * 64;
    const int n0w = (wid & 3) * 32;

    float acc[4][4][4];
    #pragma unroll
    for (int mi = 0; mi < 4; mi++)
        #pragma unroll
        for (int ni = 0; ni < 4; ni++)
            #pragma unroll
            for (int r = 0; r < 4; r++) acc[mi][ni][r] = 0.f;

    // ---- per-iter loader lambda pieces ----
    auto tap_info = [&](int tap, int& tk, size_t& woff) {
        if (IS_L2) {
            int d0 = ((child >> 2) & 1) ? ((tap >> 2) & 1) : (((tap >> 2) & 1) - 1);
            int d1 = ((child >> 1) & 1) ? ((tap >> 1) & 1) : (((tap >> 1) & 1) - 1);
            int d2 = (child & 1)        ? (tap & 1)        : ((tap & 1) - 1);
            tk = (d0 + 1) * 9 + (d1 + 1) * 3 + (d2 + 1);
            woff = (size_t)((child << 3) + tap) * (CCH * CCH);
        } else { tk = tap; woff = (size_t)tap * (CCH * CCH); }
    };

    uint4 hold[8];   // A data held across compute (32 fp32 or 64+64 bf16)

    auto issue_loads = [&](int it) {   // LDG A into hold[], cp.async B -> stage
        const int tap = it >> 1, kc = (it & 1) * KCH;
        int tk; size_t woff; tap_info(tap, tk, woff);
        // A gather
        int idx = (am < NVOX) ? nbr[am * 27 + tk] : NVOX;
        if (IS_L2) {
            const uint4* ph = (const uint4*)(srcH + (size_t)idx * CCH + kc + aseg * 32);
            const uint4* pl = (const uint4*)(srcL + (size_t)idx * CCH + kc + aseg * 32);
            #pragma unroll
            for (int q = 0; q < 4; q++) { hold[q] = ph[q]; hold[4 + q] = pl[q]; }
        } else {
            const float* ap = (idx < NVOX) ? (srcF + (size_t)idx * CCH) : g_zero;
            const uint4* p4 = (const uint4*)(ap + kc + aseg * 32);
            #pragma unroll
            for (int q = 0; q < 8; q++) hold[q] = p4[q];
        }
        // B cp.async (hi + lo), 4x16B each
        const uint32_t stb = sb + (it & 1) * STAGE;
        const int bn = tid >> 1, bhalf = tid & 1;
        const __nv_bfloat16* bsrcH = wh + woff + (size_t)bn * CCH + kc + bhalf * 32;
        const __nv_bfloat16* bsrcL = wl + woff + (size_t)bn * CCH + kc + bhalf * 32;
        uint32_t bdst = stb + 2 * TILE_B + bn * ASTRB + bhalf * 64;
        #pragma unroll
        for (int q = 0; q < 4; q++) {
            CP16(bdst + q * 16,          (const char*)bsrcH + q * 16);
            CP16(bdst + TILE_B + q * 16, (const char*)bsrcL + q * 16);
        }
        CP_COMMIT();
    };

    auto store_a = [&](int it) {       // convert (l1) + STS A from hold[]
        const uint32_t stb = sb + (it & 1) * STAGE;
        const uint32_t abase = stb + ar * ASTRB + aseg * 64;
        if (IS_L2) {
            #pragma unroll
            for (int q = 0; q < 4; q++) {
                sts128(abase + q * 16,          hold[q].x, hold[q].y, hold[q].z, hold[q].w);
                sts128(abase + TILE_B + q * 16, hold[4+q].x, hold[4+q].y, hold[4+q].z, hold[4+q].w);
            }
        } else {
            const float* f = (const float*)hold;   // 32 floats
            #pragma unroll
            for (int q = 0; q < 4; q++) {
                uint32_t hw[4], lw[4];
                #pragma unroll
                for (int p = 0; p < 4; p++) {
                    __nv_bfloat16 h0, l0, h1, l1;
                    bf16_split(f[q * 8 + p * 2],     h0, l0);
                    bf16_split(f[q * 8 + p * 2 + 1], h1, l1);
                    hw[p] = pack2(h0, h1); lw[p] = pack2(l0, l1);
                }
                sts128(abase + q * 16,          hw[0], hw[1], hw[2], hw[3]);
                sts128(abase + TILE_B + q * 16, lw[0], lw[1], lw[2], lw[3]);
            }
        }
    };

    // ---- prologue: fill stage 0 ----
    issue_loads(0);
    store_a(0);
    CP_WAIT0();
    __syncthreads();

    // ---- main loop ----
    for (int it = 0; it < niter; ++it) {
        const uint32_t stb = sb + (it & 1) * STAGE;
        const uint32_t Ah = stb, Al = stb + TILE_B, Bh = stb + 2 * TILE_B, Bl = stb + 3 * TILE_B;

        if (it + 1 < niter) issue_loads(it + 1);

        // per-thread invariant offsets
        const uint32_t aoff = g * ASTRB + t4 * 4;       // + mi*16*ASTRB (+8*ASTRB) (+16)
        const uint32_t boff = g * ASTRB + t4 * 4;       // + ni*8*ASTRB  (+ r*16)

        #pragma unroll
        for (int ks = 0; ks < 4; ks++) {
            const uint32_t kb2 = ks * 32;               // 16 bf16 = 32B per kstep
            uint32_t ah[4][4], al[4][4], bh[4][2], bl[4][2];
            #pragma unroll
            for (int mi = 0; mi < 4; mi++) {
                uint32_t ra = (m0w + mi * 16) * ASTRB + aoff + kb2;
                ah[mi][0] = lds32(Ah + ra);
                ah[mi][1] = lds32(Ah + ra + 8 * ASTRB);
                ah[mi][2] = lds32(Ah + ra + 16);
                ah[mi][3] = lds32(Ah + ra + 8 * ASTRB + 16);
                al[mi][0] = lds32(Al + ra);
                al[mi][1] = lds32(Al + ra + 8 * ASTRB);
                al[mi][2] = lds32(Al + ra + 16);
                al[mi][3] = lds32(Al + ra + 8 * ASTRB + 16);
            }
            #pragma unroll
            for (int ni = 0; ni < 4; ni++) {
                uint32_t rb = (n0w + ni * 8) * ASTRB + boff + kb2;
                bh[ni][0] = lds32(Bh + rb);
                bh[ni][1] = lds32(Bh + rb + 16);
                bl[ni][0] = lds32(Bl + rb);
                bl[ni][1] = lds32(Bl + rb + 16);
            }
            #pragma unroll
            for (int mi = 0; mi < 4; mi++)
                #pragma unroll
                for (int ni = 0; ni < 4; ni++)
                    mma_bf16(acc[mi][ni], ah[mi], bh[ni]);
            #pragma unroll
            for (int mi = 0; mi < 4; mi++)
                #pragma unroll
                for (int ni = 0; ni < 4; ni++)
                    mma_bf16(acc[mi][ni], ah[mi], bl[ni]);
            #pragma unroll
            for (int mi = 0; mi < 4; mi++)
                #pragma unroll
                for (int ni = 0; ni < 4; ni++)
                    mma_bf16(acc[mi][ni], al[mi], bh[ni]);
        }

        if (it + 1 < niter) { store_a(it + 1); CP_WAIT0(); }
        __syncthreads();
    }

    // ---- epilogue: bias + SiLU + store ----
    #pragma unroll
    for (int mi = 0; mi < 4; mi++) {
        #pragma unroll
        for (int half = 0; half < 2; half++) {
            const int gm = m0 + m0w + mi * 16 + g + half * 8;
            if (gm >= NVOX) continue;
            #pragma unroll
            for (int ni = 0; ni < 4; ni++) {
                const int col = n0w + ni * 8 + t4 * 2;
                float x0 = acc[mi][ni][half * 2 + 0] + __ldg(bias + col);
                float x1 = acc[mi][ni][half * 2 + 1] + __ldg(bias + col + 1);
                float y0 = x0 / (1.f + __expf(-x0));
                float y1 = x1 / (1.f + __expf(-x1));
                if (IS_L2) {
                    float2* op = (float2*)(outF + ((size_t)8 * gm + child) * CCH + col);
                    *op = make_float2(y0, y1);
                } else {
                    __nv_bfloat16 h0, l0, h1, l1;
                    bf16_split(y0, h0, l0); bf16_split(y1, h1, l1);
                    *(uint32_t*)(outH + (size_t)gm * CCH + col) = pack2(h0, h1);
                    *(uint32_t*)(outL + (size_t)gm * CCH + col) = pack2(l0, l1);
                }
            }
        }
    }
}

// ---------------------------------------------------------------------------
extern "C" void kernel_launch(void* const* d_in, const int* in_sizes, int n_in,
                              void* d_out, int out_size) {
    const float* feats = (const float*)d_in[0];
    const float* W1    = (const float*)d_in[1];
    const float* b1    = (const float*)d_in[2];
    const float* W2    = (const float*)d_in[3];
    const float* b2    = (const float*)d_in[4];
    const int*   nbr1  = (const int*)d_in[5];
    float* out = (float*)d_out;
    (void)in_sizes; (void)n_in; (void)out_size;

    void *h1h, *h1l, *w1h, *w1l, *wch, *wcl;
    cudaGetSymbolAddress(&h1h, g_h1h);
    cudaGetSymbolAddress(&h1l, g_h1l);
    cudaGetSymbolAddress(&w1h, g_w1h);
    cudaGetSymbolAddress(&w1l, g_w1l);
    cudaGetSymbolAddress(&wch, g_wch);
    cudaGetSymbolAddress(&wcl, g_wcl);

    cudaFuncSetAttribute(conv_mma<0>, cudaFuncAttributeMaxDynamicSharedMemorySize, SMEM_BYTES);
    cudaFuncSetAttribute(conv_mma<1>, cudaFuncAttributeMaxDynamicSharedMemorySize, SMEM_BYTES);

    prep_w1<<<(K27 * CCH * CCH + 255) / 256, 256>>>(W1);
    prep_wc<<<(64 * CCH * CCH + 255) / 256, 256>>>(W2);

    // layer 1: feats -> h1 (pre-split bf16 hi/lo)
    conv_mma<0><<<dim3(GRIDM, 1), 256, SMEM_BYTES>>>(
        feats, nullptr, nullptr, nbr1,
        (const __nv_bfloat16*)w1h, (const __nv_bfloat16*)w1l, b1,
        nullptr, (__nv_bfloat16*)h1h, (__nv_bfloat16*)h1l);

    // layer 2: h1 -> out
    conv_mma<1><<<dim3(GRIDM, 8), 256, SMEM_BYTES>>>(
        nullptr, (const __nv_bfloat16*)h1h, (const __nv_bfloat16*)h1l, nbr1,
        (const __nv_bfloat16*)wch, (const __nv_bfloat16*)wcl, b2,
        out, nullptr, nullptr);
}